// round 7
// baseline (speedup 1.0000x reference)
#include <cuda_runtime.h>
#include <math.h>

#define B_ 2
#define L_ 512
#define C_ 256
#define H_ 8
#define D_ 32
#define SCALE_ 0.17677669529663687f   // 1/sqrt(32)

typedef unsigned long long ull;

// ---------------- f32x2 packed-FMA helpers (sm_103a) ------------------------
__device__ __forceinline__ ull pack2(float a, float b) {
    ull r; asm("mov.b64 %0, {%1, %2};" : "=l"(r) : "f"(a), "f"(b)); return r;
}
__device__ __forceinline__ void unpack2(ull v, float& a, float& b) {
    asm("mov.b64 {%0, %1}, %2;" : "=f"(a), "=f"(b) : "l"(v));
}
__device__ __forceinline__ void ffma2(ull& d, ull a, ull b) {
    asm("fma.rn.f32x2 %0, %1, %2, %0;" : "+l"(d) : "l"(a), "l"(b));
}
__device__ __forceinline__ void cp16(float* smem_dst, const float* gsrc) {
    unsigned s = (unsigned)__cvta_generic_to_shared(smem_dst);
    asm volatile("cp.async.cg.shared.global [%0], [%1], 16;" :: "r"(s), "l"(gsrc) : "memory");
}
__device__ __forceinline__ void cp_commit() {
    asm volatile("cp.async.commit_group;" ::: "memory");
}

// ------------------------- scratch (device globals) -------------------------
__device__ float g_q[B_*H_*L_*D_];          // 1 MB  [b][h][l][d]
__device__ float g_k[B_*H_*L_*D_];          // 1 MB
__device__ float g_v[B_*H_*L_*D_];          // 1 MB
__device__ float g_qk[B_*L_*H_*L_];         // 16 MB [b][l][h][m]
__device__ float g_p [B_*L_*H_*L_];         // 16 MB [b][l][h][m]
__device__ float g_att[B_*L_*C_];           // 1 MB  [b][l][h*32+d]

// ===========================================================================
// K1/K5 GEMM: out[m][n] = sum_k A[m][k]*W[n][k]; 64x32 tile, 128 thr.
// ===========================================================================
__global__ __launch_bounds__(128) void gemm_kernel(
    const float* __restrict__ A, const float* __restrict__ W,
    const float* __restrict__ bias, float* __restrict__ out, int mode)
{
    __shared__ __align__(16) float As[32][68];
    __shared__ __align__(16) float Ws[32][36];
    const float* Ap = (mode == 0) ? A : g_att;
    int tid  = threadIdx.x;
    int row0 = blockIdx.x * 64;
    int col0 = blockIdx.y * 32;
    int tx = tid & 7, ty = tid >> 3;

    ull acc2[2][4];
    #pragma unroll
    for (int i = 0; i < 2; i++)
        #pragma unroll
        for (int j = 0; j < 4; j++) acc2[i][j] = 0ull;

    for (int kc = 0; kc < 256; kc += 32) {
        #pragma unroll
        for (int i = 0; i < 4; i++) {
            int idx = tid + i * 128;
            int r = idx >> 3, c4 = idx & 7;
            float4 av = *(const float4*)&Ap[(size_t)(row0 + r) * 256 + kc + c4 * 4];
            As[c4*4+0][r] = av.x; As[c4*4+1][r] = av.y;
            As[c4*4+2][r] = av.z; As[c4*4+3][r] = av.w;
        }
        #pragma unroll
        for (int i = 0; i < 2; i++) {
            int idx = tid + i * 128;
            int r = idx >> 3, c4 = idx & 7;
            float4 wv = *(const float4*)&W[(size_t)(col0 + r) * 256 + kc + c4 * 4];
            Ws[c4*4+0][r] = wv.x; Ws[c4*4+1][r] = wv.y;
            Ws[c4*4+2][r] = wv.z; Ws[c4*4+3][r] = wv.w;
        }
        __syncthreads();
        #pragma unroll
        for (int kk = 0; kk < 32; kk++) {
            ulonglong2 a2 = *(const ulonglong2*)&As[kk][ty * 4];
            float4 b4 = *(const float4*)&Ws[kk][tx * 4];
            ull bd[4] = { pack2(b4.x, b4.x), pack2(b4.y, b4.y),
                          pack2(b4.z, b4.z), pack2(b4.w, b4.w) };
            #pragma unroll
            for (int j = 0; j < 4; j++) {
                ffma2(acc2[0][j], a2.x, bd[j]);
                ffma2(acc2[1][j], a2.y, bd[j]);
            }
        }
        __syncthreads();
    }

    #pragma unroll
    for (int i2 = 0; i2 < 2; i2++) {
        #pragma unroll
        for (int j = 0; j < 4; j++) {
            float v0, v1;
            unpack2(acc2[i2][j], v0, v1);
            int n = col0 + tx * 4 + j;
            #pragma unroll
            for (int half = 0; half < 2; half++) {
                int m  = row0 + ty * 4 + i2 * 2 + half;
                float val = half ? v1 : v0;
                int bb = m >> 9, l = m & 511;
                if (mode == 0) {
                    int s = n >> 8, rem = n & 255, h = rem >> 5, d = rem & 31;
                    float* dst = (s == 0) ? g_q : (s == 1) ? g_k : g_v;
                    dst[(((size_t)bb * H_ + h) * L_ + l) * D_ + d] = val;
                } else {
                    out[(size_t)m * 256 + n] = val + bias[n];
                }
            }
        }
    }
}

// ===========================================================================
// K2: qk — block=(lt:64l, bh, mq:128m); thread owns 4l x 8m.
// Per d4: 12 LDS.128 feed 64 ffma2.
// ===========================================================================
__global__ __launch_bounds__(256, 2) void qk_kernel()
{
    __shared__ __align__(16) float ks[128 * 36];   // k quarter [128m][32d] padded
    __shared__ __align__(16) float qs[64 * 32];    // q tile    [64l][32d]
    int tid = threadIdx.x;
    int lt = blockIdx.x, bh = blockIdx.y, mq = blockIdx.z;
    int b = bh >> 3, h = bh & 7;

    const float* kb = g_k + (size_t)bh * (512 * 32) + (size_t)mq * 128 * 32;
    const float* qb = g_q + (size_t)bh * (512 * 32) + (size_t)lt * 64 * 32;

    #pragma unroll
    for (int i = 0; i < 4; i++) {
        int idx = tid + i * 256;
        int r = idx >> 3, c4 = idx & 7;
        *(float4*)&ks[r * 36 + c4 * 4] = *(const float4*)&kb[(size_t)idx * 4];
    }
    #pragma unroll
    for (int i = 0; i < 2; i++) {
        int idx = tid + i * 256;
        *(float4*)&qs[idx * 4] = *(const float4*)&qb[(size_t)idx * 4];
    }
    __syncthreads();

    int lg = tid >> 4, mg = tid & 15;   // 4 l rows, 8 m cols per thread

    ull acc[4][8];
    #pragma unroll
    for (int i = 0; i < 4; i++)
        #pragma unroll
        for (int j = 0; j < 8; j++) acc[i][j] = 0ull;

    #pragma unroll
    for (int d4 = 0; d4 < 8; d4++) {
        ulonglong2 q2[4];
        #pragma unroll
        for (int i = 0; i < 4; i++)
            q2[i] = *(const ulonglong2*)&qs[(lg * 4 + i) * 32 + d4 * 4];
        #pragma unroll
        for (int j = 0; j < 8; j++) {
            ulonglong2 kv = *(const ulonglong2*)&ks[(mg * 8 + j) * 36 + d4 * 4];
            #pragma unroll
            for (int i = 0; i < 4; i++) {
                ffma2(acc[i][j], q2[i].x, kv.x);
                ffma2(acc[i][j], q2[i].y, kv.y);
            }
        }
    }

    #pragma unroll
    for (int i = 0; i < 4; i++) {
        int l = lt * 64 + lg * 4 + i;
        float s[8];
        #pragma unroll
        for (int j = 0; j < 8; j++) {
            float lo, hi;
            unpack2(acc[i][j], lo, hi);
            s[j] = lo + hi;
        }
        float* outp = g_qk + (((size_t)b * 512 + l) * 8 + h) * 512 + mq * 128 + mg * 8;
        *(float4*)&outp[0] = make_float4(s[0], s[1], s[2], s[3]);
        *(float4*)&outp[4] = make_float4(s[4], s[5], s[6], s[7]);
    }
}

// ===========================================================================
// K3: HBM-bound hot kernel with cp.async double-buffered rp stream.
// ===========================================================================
#define RELBUF (512 * 20)
#define REL_SMEM_FLOATS (2 * RELBUF + 2048 + 8 * 512 + 40)

__global__ __launch_bounds__(256) void rel_kernel(
    const float* __restrict__ rp, const float* __restrict__ w_rel,
    const float* __restrict__ b_rel, const float* __restrict__ ln_g,
    const float* __restrict__ ln_b)
{
    extern __shared__ __align__(16) float smr[];
    float* buf0 = smr;
    float* buf1 = smr + RELBUF;
    float* wp   = smr + 2 * RELBUF;
    float* lg   = wp + 2048;
    float* par  = lg + 8 * 512;
    float* inv_s= par + 32;

    int tid = threadIdx.x;
    int bid = blockIdx.x;

    #pragma unroll
    for (int i = 0; i < 8; i++) {
        int idx = tid + i * 256;
        int e = idx & 3, h2 = (idx >> 2) & 3, c2 = idx >> 4;
        int h = 2 * h2 + (e >> 1), c = 2 * c2 + (e & 1);
        wp[idx] = w_rel[h * 256 + c];
    }
    if (tid < 8) { par[tid] = b_rel[tid]; par[8+tid] = ln_g[tid]; par[16+tid] = ln_b[tid]; }

    const float* rpb = rp + (size_t)bid * (512 * 256);
    int m0 = tid, m1 = tid + 256;

    ull raA[8], raB[8];
    #pragma unroll
    for (int h = 0; h < 8; h++) { raA[h] = 0ull; raB[h] = 0ull; }

    #pragma unroll
    for (int i = 0; i < 8; i++) {
        int idx = tid + i * 256;
        int r = idx >> 2, c4 = idx & 3;
        cp16(&buf0[r * 20 + c4 * 4], &rpb[(size_t)r * 256 + c4 * 4]);
    }
    cp_commit();

    for (int ch = 0; ch < 16; ch++) {
        float* cur = (ch & 1) ? buf1 : buf0;
        float* nxt = (ch & 1) ? buf0 : buf1;
        __syncthreads();
        if (ch + 1 < 16) {
            #pragma unroll
            for (int i = 0; i < 8; i++) {
                int idx = tid + i * 256;
                int r = idx >> 2, c4 = idx & 3;
                cp16(&nxt[r * 20 + c4 * 4],
                     &rpb[(size_t)r * 256 + (ch + 1) * 16 + c4 * 4]);
            }
            cp_commit();
            asm volatile("cp.async.wait_group 1;" ::: "memory");
        } else {
            asm volatile("cp.async.wait_group 0;" ::: "memory");
        }
        __syncthreads();

        const float* t0 = &cur[m0 * 20];
        const float* t1 = &cur[m1 * 20];
        #pragma unroll
        for (int c4 = 0; c4 < 4; c4++) {
            ulonglong2 r0 = *(const ulonglong2*)&t0[c4 * 4];
            ulonglong2 r1 = *(const ulonglong2*)&t1[c4 * 4];
            int g2 = ch * 8 + c4 * 2;
            #pragma unroll
            for (int h2 = 0; h2 < 4; h2++) {
                ulonglong2 wA = *(const ulonglong2*)&wp[(g2 * 4 + h2) * 4];
                ulonglong2 wB = *(const ulonglong2*)&wp[((g2 + 1) * 4 + h2) * 4];
                ffma2(raA[2*h2],   r0.x, wA.x); ffma2(raA[2*h2+1], r0.x, wA.y);
                ffma2(raA[2*h2],   r0.y, wB.x); ffma2(raA[2*h2+1], r0.y, wB.y);
                ffma2(raB[2*h2],   r1.x, wA.x); ffma2(raB[2*h2+1], r1.x, wA.y);
                ffma2(raB[2*h2],   r1.y, wB.x); ffma2(raB[2*h2+1], r1.y, wB.y);
            }
        }
    }

    float relA[8], relB[8];
    {
        float muA = 0.f, muB = 0.f;
        #pragma unroll
        for (int h = 0; h < 8; h++) {
            float lo, hi;
            unpack2(raA[h], lo, hi);
            float xv = lo + hi + par[h];
            relA[h] = 0.5f * xv * (1.f + erff(xv * 0.7071067811865475f));
            muA += relA[h];
            unpack2(raB[h], lo, hi);
            xv = lo + hi + par[h];
            relB[h] = 0.5f * xv * (1.f + erff(xv * 0.7071067811865475f));
            muB += relB[h];
        }
        muA *= 0.125f; muB *= 0.125f;
        float vA = 0.f, vB = 0.f;
        #pragma unroll
        for (int h = 0; h < 8; h++) {
            float dA = relA[h] - muA; vA += dA * dA;
            float dB = relB[h] - muB; vB += dB * dB;
        }
        float rA = rsqrtf(vA * 0.125f + 1e-5f), rB = rsqrtf(vB * 0.125f + 1e-5f);
        #pragma unroll
        for (int h = 0; h < 8; h++) {
            relA[h] = (relA[h] - muA) * rA * par[8+h] + par[16+h];
            relB[h] = (relB[h] - muB) * rB * par[8+h] + par[16+h];
        }
    }

    const float* qkb = g_qk + (size_t)bid * 4096;
    #pragma unroll
    for (int h = 0; h < 8; h++) {
        lg[h * 512 + m0] = (qkb[h * 512 + m0] + relA[h]) * SCALE_;
        lg[h * 512 + m1] = (qkb[h * 512 + m1] + relB[h]) * SCALE_;
    }
    __syncthreads();

    {
        int lane = tid & 31, h = tid >> 5;
        float* row = &lg[h * 512];
        float vals[16];
        float mx = -1e30f;
        #pragma unroll
        for (int j = 0; j < 16; j++) { vals[j] = row[lane + 32 * j]; mx = fmaxf(mx, vals[j]); }
        #pragma unroll
        for (int o = 16; o > 0; o >>= 1) mx = fmaxf(mx, __shfl_xor_sync(0xffffffff, mx, o));
        float sum = 0.f;
        #pragma unroll
        for (int j = 0; j < 16; j++) {
            float e = __expf(vals[j] - mx);
            row[lane + 32 * j] = e;
            sum += e;
        }
        #pragma unroll
        for (int o = 16; o > 0; o >>= 1) sum += __shfl_xor_sync(0xffffffff, sum, o);
        if (lane == 0) inv_s[h] = 1.f / sum;
    }
    __syncthreads();

    float* pb = g_p + (size_t)bid * 4096;
    #pragma unroll
    for (int i = 0; i < 4; i++) {
        int idx4 = tid + i * 256;
        int h = idx4 >> 7;
        float4 v = *(const float4*)&lg[h * 512 + (idx4 & 127) * 4];
        float inv = inv_s[h];
        v.x *= inv; v.y *= inv; v.z *= inv; v.w *= inv;
        *(float4*)&pb[(size_t)idx4 * 4] = v;
    }
}

// ===========================================================================
// K4: PV — block=(lt:64l, bh); v staged ONCE; thread owns 2l x d-quad.
// Per m4: 6 LDS.128 feed 16 ffma2.
// ===========================================================================
#define PV_SMEM_FLOATS (512 * 36)

__global__ __launch_bounds__(256) void pv_kernel()
{
    extern __shared__ __align__(16) float vs[];    // [512][36]
    int tid = threadIdx.x;
    int lt = blockIdx.x, bh = blockIdx.y;
    int b = bh >> 3, h = bh & 7;

    const float* vb = g_v + (size_t)bh * (512 * 32);
    #pragma unroll
    for (int i = 0; i < 16; i++) {
        int idx = tid + i * 256;
        int r = idx >> 3, c4 = idx & 7;
        *(float4*)&vs[r * 36 + c4 * 4] = *(const float4*)&vb[(size_t)idx * 4];
    }
    __syncthreads();

    int lg = tid >> 3, dq = tid & 7;
    int l0 = lt * 64 + lg * 2;
    const float* p0 = g_p + (((size_t)b * 512 + l0) * 8 + h) * 512;
    const float* p1 = p0 + 8 * 512;

    ull a00 = 0ull, a01 = 0ull, a10 = 0ull, a11 = 0ull;
    #pragma unroll 4
    for (int m4 = 0; m4 < 128; m4++) {
        float4 q0 = *(const float4*)&p0[m4 * 4];
        float4 q1 = *(const float4*)&p1[m4 * 4];
        float pv0[4] = {q0.x, q0.y, q0.z, q0.w};
        float pv1[4] = {q1.x, q1.y, q1.z, q1.w};
        #pragma unroll
        for (int s = 0; s < 4; s++) {
            ulonglong2 v2 = *(const ulonglong2*)&vs[(m4 * 4 + s) * 36 + dq * 4];
            ull pd0 = pack2(pv0[s], pv0[s]);
            ull pd1 = pack2(pv1[s], pv1[s]);
            ffma2(a00, pd0, v2.x); ffma2(a01, pd0, v2.y);
            ffma2(a10, pd1, v2.x); ffma2(a11, pd1, v2.y);
        }
    }
    float o0, o1, o2, o3;
    unpack2(a00, o0, o1); unpack2(a01, o2, o3);
    *(float4*)&g_att[((size_t)b * 512 + l0) * 256 + h * 32 + dq * 4] =
        make_float4(o0, o1, o2, o3);
    unpack2(a10, o0, o1); unpack2(a11, o2, o3);
    *(float4*)&g_att[((size_t)b * 512 + l0 + 1) * 256 + h * 32 + dq * 4] =
        make_float4(o0, o1, o2, o3);
}

// ===========================================================================
extern "C" void kernel_launch(void* const* d_in, const int* in_sizes, int n_in,
                              void* d_out, int out_size)
{
    const float* x      = (const float*)d_in[0];
    const float* rp     = (const float*)d_in[1];
    const float* w_qkv  = (const float*)d_in[2];
    const float* w_rel  = (const float*)d_in[3];
    const float* b_rel  = (const float*)d_in[4];
    const float* ln_g   = (const float*)d_in[5];
    const float* ln_b   = (const float*)d_in[6];
    const float* w_proj = (const float*)d_in[7];
    const float* b_proj = (const float*)d_in[8];
    float* out = (float*)d_out;

    int rel_smem = REL_SMEM_FLOATS * (int)sizeof(float);
    int pv_smem  = PV_SMEM_FLOATS * (int)sizeof(float);
    cudaFuncSetAttribute(rel_kernel, cudaFuncAttributeMaxDynamicSharedMemorySize, rel_smem);
    cudaFuncSetAttribute(pv_kernel,  cudaFuncAttributeMaxDynamicSharedMemorySize, pv_smem);

    // K1: qkv projection
    gemm_kernel<<<dim3(16, 24), 128>>>(x, w_qkv, nullptr, nullptr, 0);
    // K2: qk logits (grid 512, 4lx8m per thread)
    qk_kernel<<<dim3(8, 16, 4), 256>>>();
    // K3: rel bias + softmax (HBM-bound, cp.async pipelined)
    rel_kernel<<<1024, 256, rel_smem>>>(rp, w_rel, b_rel, ln_g, ln_b);
    // K4: PV (grid 128, v staged once, 2l per thread)
    pv_kernel<<<dim3(8, 16), 256, pv_smem>>>();
    // K5: output projection + bias
    gemm_kernel<<<dim3(16, 8), 128>>>(nullptr, w_proj, b_proj, out, 1);
}

// round 8
// speedup vs baseline: 1.1259x; 1.1259x over previous
#include <cuda_runtime.h>
#include <math.h>

#define B_ 2
#define L_ 512
#define C_ 256
#define H_ 8
#define D_ 32
#define SCALE_ 0.17677669529663687f   // 1/sqrt(32)

typedef unsigned long long ull;

// ---------------- f32x2 packed-FMA helpers (sm_103a) ------------------------
__device__ __forceinline__ ull pack2(float a, float b) {
    ull r; asm("mov.b64 %0, {%1, %2};" : "=l"(r) : "f"(a), "f"(b)); return r;
}
__device__ __forceinline__ void unpack2(ull v, float& a, float& b) {
    asm("mov.b64 {%0, %1}, %2;" : "=f"(a), "=f"(b) : "l"(v));
}
__device__ __forceinline__ void ffma2(ull& d, ull a, ull b) {
    asm("fma.rn.f32x2 %0, %1, %2, %0;" : "+l"(d) : "l"(a), "l"(b));
}

// ------------------------- scratch (device globals) -------------------------
__device__ float g_q[B_*H_*L_*D_];          // 1 MB  [b][h][l][d]
__device__ float g_k[B_*H_*L_*D_];          // 1 MB
__device__ float g_v[B_*H_*L_*D_];          // 1 MB
__device__ float g_qk[B_*L_*H_*L_];         // 16 MB [b][l][h][m]
__device__ float g_rel[B_*L_*H_*L_];        // 16 MB [b][l][h][m]
__device__ float g_att[B_*L_*C_];           // 1 MB  [b][l][h*32+d]

// ===========================================================================
// GEMM (round-2 proven): out[m][n] = sum_k A[m][k]*W[n][k]; 64x32, 128 thr.
// mode 0: A=x -> scatter g_q/g_k/g_v.   mode 1: A=g_att, +bias -> out.
// ===========================================================================
__global__ __launch_bounds__(128) void gemm_kernel(
    const float* __restrict__ A, const float* __restrict__ W,
    const float* __restrict__ bias, float* __restrict__ out, int mode)
{
    __shared__ __align__(16) float As[32][68];
    __shared__ __align__(16) float Ws[32][36];
    const float* Ap = (mode == 0) ? A : g_att;
    int tid  = threadIdx.x;
    int row0 = blockIdx.x * 64;
    int col0 = blockIdx.y * 32;
    int tx = tid & 7, ty = tid >> 3;

    ull acc2[2][4];
    #pragma unroll
    for (int i = 0; i < 2; i++)
        #pragma unroll
        for (int j = 0; j < 4; j++) acc2[i][j] = 0ull;

    for (int kc = 0; kc < 256; kc += 32) {
        #pragma unroll
        for (int i = 0; i < 4; i++) {
            int idx = tid + i * 128;
            int r = idx >> 3, c4 = idx & 7;
            float4 av = *(const float4*)&Ap[(size_t)(row0 + r) * 256 + kc + c4 * 4];
            As[c4*4+0][r] = av.x; As[c4*4+1][r] = av.y;
            As[c4*4+2][r] = av.z; As[c4*4+3][r] = av.w;
        }
        #pragma unroll
        for (int i = 0; i < 2; i++) {
            int idx = tid + i * 128;
            int r = idx >> 3, c4 = idx & 7;
            float4 wv = *(const float4*)&W[(size_t)(col0 + r) * 256 + kc + c4 * 4];
            Ws[c4*4+0][r] = wv.x; Ws[c4*4+1][r] = wv.y;
            Ws[c4*4+2][r] = wv.z; Ws[c4*4+3][r] = wv.w;
        }
        __syncthreads();
        #pragma unroll
        for (int kk = 0; kk < 32; kk++) {
            ulonglong2 a2 = *(const ulonglong2*)&As[kk][ty * 4];
            float4 b4 = *(const float4*)&Ws[kk][tx * 4];
            ull bd[4] = { pack2(b4.x, b4.x), pack2(b4.y, b4.y),
                          pack2(b4.z, b4.z), pack2(b4.w, b4.w) };
            #pragma unroll
            for (int j = 0; j < 4; j++) {
                ffma2(acc2[0][j], a2.x, bd[j]);
                ffma2(acc2[1][j], a2.y, bd[j]);
            }
        }
        __syncthreads();
    }

    #pragma unroll
    for (int i2 = 0; i2 < 2; i2++) {
        #pragma unroll
        for (int j = 0; j < 4; j++) {
            float v0, v1;
            unpack2(acc2[i2][j], v0, v1);
            int n = col0 + tx * 4 + j;
            #pragma unroll
            for (int half = 0; half < 2; half++) {
                int m  = row0 + ty * 4 + i2 * 2 + half;
                float val = half ? v1 : v0;
                int bb = m >> 9, l = m & 511;
                if (mode == 0) {
                    int s = n >> 8, rem = n & 255, h = rem >> 5, d = rem & 31;
                    float* dst = (s == 0) ? g_q : (s == 1) ? g_k : g_v;
                    dst[(((size_t)bb * H_ + h) * L_ + l) * D_ + d] = val;
                } else {
                    out[(size_t)m * 256 + n] = val + bias[n];
                }
            }
        }
    }
}

// ===========================================================================
// qk (round-6 proven): block=(lt32, bh, mhalf); writes g_qk[b,l,h,m].
// ===========================================================================
__global__ __launch_bounds__(256) void qk_kernel()
{
    __shared__ __align__(16) float ks[256 * 36];
    __shared__ __align__(16) float qs[32 * 32];
    int tid = threadIdx.x;
    int bh = blockIdx.y, lt = blockIdx.x, mh = blockIdx.z;
    int b = bh >> 3, h = bh & 7;

    const float* kb = g_k + (size_t)bh * (512 * 32) + (size_t)mh * 256 * 32;
    const float* qb = g_q + (size_t)bh * (512 * 32) + (size_t)lt * 32 * 32;

    #pragma unroll
    for (int i = 0; i < 8; i++) {
        int idx = tid + i * 256;
        int r = idx >> 3, c4 = idx & 7;
        *(float4*)&ks[r * 36 + c4 * 4] = *(const float4*)&kb[(size_t)idx * 4];
    }
    { int r = tid >> 3, c4 = tid & 7;
      *(float4*)&qs[r * 32 + c4 * 4] = *(const float4*)&qb[(size_t)tid * 4]; }
    __syncthreads();

    int l = tid >> 3, mg = tid & 7;
    ull q2[16];
    #pragma unroll
    for (int j = 0; j < 8; j++) {
        ulonglong2 t = *(const ulonglong2*)&qs[l * 32 + j * 4];
        q2[2*j] = t.x; q2[2*j+1] = t.y;
    }
    float* outp = g_qk + (((size_t)b * 512 + lt * 32 + l) * 8 + h) * 512 + mh * 256;
    #pragma unroll 4
    for (int i = 0; i < 32; i++) {
        int m = mg + i * 8;
        ull sa = 0ull, sb = 0ull;
        #pragma unroll
        for (int j = 0; j < 8; j++) {
            ulonglong2 kv = *(const ulonglong2*)&ks[m * 36 + j * 4];
            ffma2(sa, q2[2*j], kv.x);
            ffma2(sb, q2[2*j+1], kv.y);
        }
        float a0, a1, b0, b1;
        unpack2(sa, a0, a1); unpack2(sb, b0, b1);
        outp[m] = (a0 + a1) + (b0 + b1);
    }
}

// ===========================================================================
// relcompute (round-2 proven core, softmax removed): block = 256 rows of the
// 524288 (b,l,m) rows; GELU+LN; writes g_rel[b,l,h,m].  The HBM hot kernel.
// ===========================================================================
__global__ __launch_bounds__(256, 4) void rel_kernel(
    const float* __restrict__ rp, const float* __restrict__ w_rel,
    const float* __restrict__ b_rel, const float* __restrict__ ln_g,
    const float* __restrict__ ln_b)
{
    __shared__ __align__(16) float tile[256 * 36];
    __shared__ __align__(16) float ws[256 * 8];     // ws[c*8 + h]
    __shared__ float par[24];
    int tid = threadIdx.x;

    #pragma unroll
    for (int i = 0; i < 8; i++) {
        int idx = tid + i * 256;                     // idx = h*256 + c
        ws[(idx & 255) * 8 + (idx >> 8)] = w_rel[idx];
    }
    if (tid < 8) { par[tid] = b_rel[tid]; par[8+tid] = ln_g[tid]; par[16+tid] = ln_b[tid]; }

    ull acc2[4] = {0ull, 0ull, 0ull, 0ull};         // h pairs (0,1)(2,3)(4,5)(6,7)
    const float* rowp = rp + (size_t)blockIdx.x * (256 * 256);
    __syncthreads();

    for (int ch = 0; ch < 8; ch++) {
        #pragma unroll
        for (int i = 0; i < 8; i++) {
            int idx = tid + i * 256;
            int rr = idx >> 3, c4 = idx & 7;
            float4 v = *(const float4*)&rowp[(size_t)rr * 256 + ch * 32 + c4 * 4];
            *(float4*)&tile[rr * 36 + c4 * 4] = v;
        }
        __syncthreads();
        const float* trow = &tile[tid * 36];
        #pragma unroll
        for (int c = 0; c < 32; c += 4) {
            float4 r4 = *(const float4*)&trow[c];
            float rv[4] = {r4.x, r4.y, r4.z, r4.w};
            #pragma unroll
            for (int u = 0; u < 4; u++) {
                ull rd = pack2(rv[u], rv[u]);
                ulonglong2 w01 = *(const ulonglong2*)&ws[(ch * 32 + c + u) * 8];
                ulonglong2 w23 = *(const ulonglong2*)&ws[(ch * 32 + c + u) * 8 + 4];
                ffma2(acc2[0], rd, w01.x);
                ffma2(acc2[1], rd, w01.y);
                ffma2(acc2[2], rd, w23.x);
                ffma2(acc2[3], rd, w23.y);
            }
        }
        __syncthreads();
    }

    float acc[8];
    #pragma unroll
    for (int p = 0; p < 4; p++) unpack2(acc2[p], acc[2*p], acc[2*p+1]);

    float gv[8];
    float mu = 0.f;
    #pragma unroll
    for (int h = 0; h < 8; h++) {
        float xv = acc[h] + par[h];
        gv[h] = 0.5f * xv * (1.f + erff(xv * 0.7071067811865475f));
        mu += gv[h];
    }
    mu *= 0.125f;
    float var = 0.f;
    #pragma unroll
    for (int h = 0; h < 8; h++) { float d = gv[h] - mu; var += d * d; }
    var *= 0.125f;
    float rstd = rsqrtf(var + 1e-5f);

    size_t r = (size_t)blockIdx.x * 256 + tid;      // global (b,l,m) row
    size_t base = (r >> 9) * 4096 + (r & 511);      // [b,l][h][m]
    #pragma unroll
    for (int h = 0; h < 8; h++)
        g_rel[base + (size_t)h * 512] = (gv[h] - mu) * rstd * par[8 + h] + par[16 + h];
}

// ===========================================================================
// attn2: fused (qk+rel)->softmax->PV.  block=(lt:16 l-rows, bh); 256 thr.
// Reads contiguous qk/rel rows, stages v once, writes g_att.  No g_p.
// ===========================================================================
#define AT_LG 520
#define ATTN2_SMEM_FLOATS (16 * AT_LG + 512 * 36 + 16)

__global__ __launch_bounds__(256) void attn2_kernel()
{
    extern __shared__ __align__(16) float sm2[];
    float* lg    = sm2;                       // [16][520]
    float* vs    = sm2 + 16 * AT_LG;          // [512][36]
    float* inv_s = vs + 512 * 36;             // [16]
    int tid = threadIdx.x;
    int lt = blockIdx.x, bh = blockIdx.y;
    int b = bh >> 3, h = bh & 7;

    // stage v whole
    const float* vb = g_v + (size_t)bh * (512 * 32);
    #pragma unroll
    for (int i = 0; i < 16; i++) {
        int idx = tid + i * 256;
        int r = idx >> 3, c4 = idx & 7;
        *(float4*)&vs[r * 36 + c4 * 4] = *(const float4*)&vb[(size_t)idx * 4];
    }

    // logits = (qk + rel) * scale   (16 rows x 512, fully coalesced reads)
    size_t base = ((size_t)(b * 512) + lt * 16) * 4096 + (size_t)h * 512;
    #pragma unroll
    for (int j = 0; j < 8; j++) {
        int idx = tid + j * 256;                 // [0, 2048)
        int row = idx >> 7, col4 = idx & 127;
        size_t g = base + (size_t)row * 4096 + col4 * 4;
        float4 a = *(const float4*)&g_qk[g];
        float4 c = *(const float4*)&g_rel[g];
        float4 o;
        o.x = (a.x + c.x) * SCALE_; o.y = (a.y + c.y) * SCALE_;
        o.z = (a.z + c.z) * SCALE_; o.w = (a.w + c.w) * SCALE_;
        *(float4*)&lg[row * AT_LG + col4 * 4] = o;
    }
    __syncthreads();

    // softmax: warp w handles rows 2w, 2w+1
    {
        int lane = tid & 31, w = tid >> 5;
        #pragma unroll
        for (int rr = 0; rr < 2; rr++) {
            float* row = &lg[(w * 2 + rr) * AT_LG];
            float vals[16];
            float mx = -1e30f;
            #pragma unroll
            for (int j = 0; j < 16; j++) { vals[j] = row[lane + 32 * j]; mx = fmaxf(mx, vals[j]); }
            #pragma unroll
            for (int o = 16; o > 0; o >>= 1) mx = fmaxf(mx, __shfl_xor_sync(0xffffffff, mx, o));
            float sum = 0.f;
            #pragma unroll
            for (int j = 0; j < 16; j++) {
                float e = __expf(vals[j] - mx);
                row[lane + 32 * j] = e;
                sum += e;
            }
            #pragma unroll
            for (int o = 16; o > 0; o >>= 1) sum += __shfl_xor_sync(0xffffffff, sum, o);
            if (lane == 0) inv_s[w * 2 + rr] = 1.f / sum;
        }
    }
    __syncthreads();

    // PV: thread = (l = tid>>4, d-pair dp = tid&15)
    {
        int l = tid >> 4, dp = tid & 15;
        const float* lrow = &lg[l * AT_LG];
        ull acc = 0ull;
        #pragma unroll 4
        for (int m4 = 0; m4 < 128; m4++) {
            float4 p4 = *(const float4*)&lrow[m4 * 4];
            float pv[4] = {p4.x, p4.y, p4.z, p4.w};
            #pragma unroll
            for (int s = 0; s < 4; s++) {
                ull vv = *(const ull*)&vs[(m4 * 4 + s) * 36 + dp * 2];
                ffma2(acc, pack2(pv[s], pv[s]), vv);
            }
        }
        float o0, o1;
        unpack2(acc, o0, o1);
        float inv = inv_s[l];
        float2 o = make_float2(o0 * inv, o1 * inv);
        *(float2*)&g_att[((size_t)(b * 512) + lt * 16 + l) * 256 + h * 32 + dp * 2] = o;
    }
}

// ===========================================================================
extern "C" void kernel_launch(void* const* d_in, const int* in_sizes, int n_in,
                              void* d_out, int out_size)
{
    const float* x      = (const float*)d_in[0];
    const float* rp     = (const float*)d_in[1];
    const float* w_qkv  = (const float*)d_in[2];
    const float* w_rel  = (const float*)d_in[3];
    const float* b_rel  = (const float*)d_in[4];
    const float* ln_g   = (const float*)d_in[5];
    const float* ln_b   = (const float*)d_in[6];
    const float* w_proj = (const float*)d_in[7];
    const float* b_proj = (const float*)d_in[8];
    float* out = (float*)d_out;

    static bool s_init = false;
    static cudaStream_t s_sB;
    static cudaEvent_t s_evF, s_evJ;
    if (!s_init) {
        cudaStreamCreateWithFlags(&s_sB, cudaStreamNonBlocking);
        cudaEventCreateWithFlags(&s_evF, cudaEventDisableTiming);
        cudaEventCreateWithFlags(&s_evJ, cudaEventDisableTiming);
        cudaFuncSetAttribute(attn2_kernel, cudaFuncAttributeMaxDynamicSharedMemorySize,
                             ATTN2_SMEM_FLOATS * (int)sizeof(float));
        s_init = true;
    }

    // fork: side stream runs qkv-gemm + qk while main stream runs relcompute
    cudaEventRecord(s_evF, 0);
    cudaStreamWaitEvent(s_sB, s_evF, 0);

    gemm_kernel<<<dim3(16, 24), 128, 0, s_sB>>>(x, w_qkv, nullptr, nullptr, 0);
    qk_kernel<<<dim3(16, 16, 2), 256, 0, s_sB>>>();

    rel_kernel<<<2048, 256>>>(rp, w_rel, b_rel, ln_g, ln_b);   // main stream

    // join
    cudaEventRecord(s_evJ, s_sB);
    cudaStreamWaitEvent(0, s_evJ, 0);

    attn2_kernel<<<dim3(32, 16), 256, ATTN2_SMEM_FLOATS * (int)sizeof(float)>>>();
    gemm_kernel<<<dim3(16, 8), 128>>>(nullptr, w_proj, b_proj, out, 1);
}

// round 9
// speedup vs baseline: 1.1325x; 1.0059x over previous
#include <cuda_runtime.h>
#include <math.h>

#define B_ 2
#define L_ 512
#define C_ 256
#define H_ 8
#define D_ 32
#define SCALE_ 0.17677669529663687f   // 1/sqrt(32)

typedef unsigned long long ull;

// ---------------- f32x2 packed-FMA helpers (sm_103a) ------------------------
__device__ __forceinline__ ull pack2(float a, float b) {
    ull r; asm("mov.b64 %0, {%1, %2};" : "=l"(r) : "f"(a), "f"(b)); return r;
}
__device__ __forceinline__ void unpack2(ull v, float& a, float& b) {
    asm("mov.b64 {%0, %1}, %2;" : "=f"(a), "=f"(b) : "l"(v));
}
__device__ __forceinline__ void ffma2(ull& d, ull a, ull b) {
    asm("fma.rn.f32x2 %0, %1, %2, %0;" : "+l"(d) : "l"(a), "l"(b));
}

// ------------------------- scratch (device globals) -------------------------
__device__ float g_q[B_*H_*L_*D_];          // 1 MB  [b][h][l][d]
__device__ float g_k[B_*H_*L_*D_];          // 1 MB
__device__ float g_v[B_*H_*L_*D_];          // 1 MB
__device__ float g_qk[B_*L_*H_*L_];         // 16 MB [b][l][h][m]
__device__ float g_rel[B_*L_*H_*L_];        // 16 MB [b][l][h][m]
__device__ float g_att[B_*L_*C_];           // 1 MB  [b][l][h*32+d]

// ===========================================================================
// GEMM (round-2 proven): out[m][n] = sum_k A[m][k]*W[n][k]; 64x32, 128 thr.
// mode 0: A=x -> scatter g_q/g_k/g_v.   mode 1: A=g_att, +bias -> out.
// ===========================================================================
__global__ __launch_bounds__(128) void gemm_kernel(
    const float* __restrict__ A, const float* __restrict__ W,
    const float* __restrict__ bias, float* __restrict__ out, int mode)
{
    __shared__ __align__(16) float As[32][68];
    __shared__ __align__(16) float Ws[32][36];
    const float* Ap = (mode == 0) ? A : g_att;
    int tid  = threadIdx.x;
    int row0 = blockIdx.x * 64;
    int col0 = blockIdx.y * 32;
    int tx = tid & 7, ty = tid >> 3;

    ull acc2[2][4];
    #pragma unroll
    for (int i = 0; i < 2; i++)
        #pragma unroll
        for (int j = 0; j < 4; j++) acc2[i][j] = 0ull;

    for (int kc = 0; kc < 256; kc += 32) {
        #pragma unroll
        for (int i = 0; i < 4; i++) {
            int idx = tid + i * 128;
            int r = idx >> 3, c4 = idx & 7;
            float4 av = *(const float4*)&Ap[(size_t)(row0 + r) * 256 + kc + c4 * 4];
            As[c4*4+0][r] = av.x; As[c4*4+1][r] = av.y;
            As[c4*4+2][r] = av.z; As[c4*4+3][r] = av.w;
        }
        #pragma unroll
        for (int i = 0; i < 2; i++) {
            int idx = tid + i * 128;
            int r = idx >> 3, c4 = idx & 7;
            float4 wv = *(const float4*)&W[(size_t)(col0 + r) * 256 + kc + c4 * 4];
            Ws[c4*4+0][r] = wv.x; Ws[c4*4+1][r] = wv.y;
            Ws[c4*4+2][r] = wv.z; Ws[c4*4+3][r] = wv.w;
        }
        __syncthreads();
        #pragma unroll
        for (int kk = 0; kk < 32; kk++) {
            ulonglong2 a2 = *(const ulonglong2*)&As[kk][ty * 4];
            float4 b4 = *(const float4*)&Ws[kk][tx * 4];
            ull bd[4] = { pack2(b4.x, b4.x), pack2(b4.y, b4.y),
                          pack2(b4.z, b4.z), pack2(b4.w, b4.w) };
            #pragma unroll
            for (int j = 0; j < 4; j++) {
                ffma2(acc2[0][j], a2.x, bd[j]);
                ffma2(acc2[1][j], a2.y, bd[j]);
            }
        }
        __syncthreads();
    }

    #pragma unroll
    for (int i2 = 0; i2 < 2; i2++) {
        #pragma unroll
        for (int j = 0; j < 4; j++) {
            float v0, v1;
            unpack2(acc2[i2][j], v0, v1);
            int n = col0 + tx * 4 + j;
            #pragma unroll
            for (int half = 0; half < 2; half++) {
                int m  = row0 + ty * 4 + i2 * 2 + half;
                float val = half ? v1 : v0;
                int bb = m >> 9, l = m & 511;
                if (mode == 0) {
                    int s = n >> 8, rem = n & 255, h = rem >> 5, d = rem & 31;
                    float* dst = (s == 0) ? g_q : (s == 1) ? g_k : g_v;
                    dst[(((size_t)bb * H_ + h) * L_ + l) * D_ + d] = val;
                } else {
                    out[(size_t)m * 256 + n] = val + bias[n];
                }
            }
        }
    }
}

// ===========================================================================
// qk (round-6 proven): block=(lt32, bh, mhalf); writes g_qk[b,l,h,m].
// ===========================================================================
__global__ __launch_bounds__(256) void qk_kernel()
{
    __shared__ __align__(16) float ks[256 * 36];
    __shared__ __align__(16) float qs[32 * 32];
    int tid = threadIdx.x;
    int bh = blockIdx.y, lt = blockIdx.x, mh = blockIdx.z;
    int b = bh >> 3, h = bh & 7;

    const float* kb = g_k + (size_t)bh * (512 * 32) + (size_t)mh * 256 * 32;
    const float* qb = g_q + (size_t)bh * (512 * 32) + (size_t)lt * 32 * 32;

    #pragma unroll
    for (int i = 0; i < 8; i++) {
        int idx = tid + i * 256;
        int r = idx >> 3, c4 = idx & 7;
        *(float4*)&ks[r * 36 + c4 * 4] = *(const float4*)&kb[(size_t)idx * 4];
    }
    { int r = tid >> 3, c4 = tid & 7;
      *(float4*)&qs[r * 32 + c4 * 4] = *(const float4*)&qb[(size_t)tid * 4]; }
    __syncthreads();

    int l = tid >> 3, mg = tid & 7;
    ull q2[16];
    #pragma unroll
    for (int j = 0; j < 8; j++) {
        ulonglong2 t = *(const ulonglong2*)&qs[l * 32 + j * 4];
        q2[2*j] = t.x; q2[2*j+1] = t.y;
    }
    float* outp = g_qk + (((size_t)b * 512 + lt * 32 + l) * 8 + h) * 512 + mh * 256;
    #pragma unroll 4
    for (int i = 0; i < 32; i++) {
        int m = mg + i * 8;
        ull sa = 0ull, sb = 0ull;
        #pragma unroll
        for (int j = 0; j < 8; j++) {
            ulonglong2 kv = *(const ulonglong2*)&ks[m * 36 + j * 4];
            ffma2(sa, q2[2*j], kv.x);
            ffma2(sb, q2[2*j+1], kv.y);
        }
        float a0, a1, b0, b1;
        unpack2(sa, a0, a1); unpack2(sb, b0, b1);
        outp[m] = (a0 + a1) + (b0 + b1);
    }
}

// ===========================================================================
// relcompute (round-8 proven): GELU+LN; writes g_rel[b,l,h,m].  DRAM-bound.
// ===========================================================================
__global__ __launch_bounds__(256, 4) void rel_kernel(
    const float* __restrict__ rp, const float* __restrict__ w_rel,
    const float* __restrict__ b_rel, const float* __restrict__ ln_g,
    const float* __restrict__ ln_b)
{
    __shared__ __align__(16) float tile[256 * 36];
    __shared__ __align__(16) float ws[256 * 8];     // ws[c*8 + h]
    __shared__ float par[24];
    int tid = threadIdx.x;

    #pragma unroll
    for (int i = 0; i < 8; i++) {
        int idx = tid + i * 256;                     // idx = h*256 + c
        ws[(idx & 255) * 8 + (idx >> 8)] = w_rel[idx];
    }
    if (tid < 8) { par[tid] = b_rel[tid]; par[8+tid] = ln_g[tid]; par[16+tid] = ln_b[tid]; }

    ull acc2[4] = {0ull, 0ull, 0ull, 0ull};         // h pairs
    const float* rowp = rp + (size_t)blockIdx.x * (256 * 256);
    __syncthreads();

    for (int ch = 0; ch < 8; ch++) {
        #pragma unroll
        for (int i = 0; i < 8; i++) {
            int idx = tid + i * 256;
            int rr = idx >> 3, c4 = idx & 7;
            float4 v = *(const float4*)&rowp[(size_t)rr * 256 + ch * 32 + c4 * 4];
            *(float4*)&tile[rr * 36 + c4 * 4] = v;
        }
        __syncthreads();
        const float* trow = &tile[tid * 36];
        #pragma unroll
        for (int c = 0; c < 32; c += 4) {
            float4 r4 = *(const float4*)&trow[c];
            float rv[4] = {r4.x, r4.y, r4.z, r4.w};
            #pragma unroll
            for (int u = 0; u < 4; u++) {
                ull rd = pack2(rv[u], rv[u]);
                ulonglong2 w01 = *(const ulonglong2*)&ws[(ch * 32 + c + u) * 8];
                ulonglong2 w23 = *(const ulonglong2*)&ws[(ch * 32 + c + u) * 8 + 4];
                ffma2(acc2[0], rd, w01.x);
                ffma2(acc2[1], rd, w01.y);
                ffma2(acc2[2], rd, w23.x);
                ffma2(acc2[3], rd, w23.y);
            }
        }
        __syncthreads();
    }

    float acc[8];
    #pragma unroll
    for (int p = 0; p < 4; p++) unpack2(acc2[p], acc[2*p], acc[2*p+1]);

    float gv[8];
    float mu = 0.f;
    #pragma unroll
    for (int h = 0; h < 8; h++) {
        float xv = acc[h] + par[h];
        gv[h] = 0.5f * xv * (1.f + erff(xv * 0.7071067811865475f));
        mu += gv[h];
    }
    mu *= 0.125f;
    float var = 0.f;
    #pragma unroll
    for (int h = 0; h < 8; h++) { float d = gv[h] - mu; var += d * d; }
    var *= 0.125f;
    float rstd = rsqrtf(var + 1e-5f);

    size_t r = (size_t)blockIdx.x * 256 + tid;
    size_t base = (r >> 9) * 4096 + (r & 511);
    #pragma unroll
    for (int h = 0; h < 8; h++)
        g_rel[base + (size_t)h * 512] = (gv[h] - mu) * rstd * par[8 + h] + par[16 + h];
}

// ===========================================================================
// attn2 v2: fused (qk+rel)->softmax->PV with CHUNKED v staging (4 x 128 rows)
// smem 51.8 KB -> 4 blocks/SM (was 81.5 KB / 2 blocks).
// ===========================================================================
#define AT_LG 520
#define ATTN2_SMEM_FLOATS (16 * AT_LG + 128 * 36 + 16)

__global__ __launch_bounds__(256) void attn2_kernel()
{
    extern __shared__ __align__(16) float sm2[];
    float* lg    = sm2;                       // [16][520]  33.3 KB
    float* vs    = sm2 + 16 * AT_LG;          // [128][36]  18.4 KB (chunk)
    float* inv_s = vs + 128 * 36;             // [16]
    int tid = threadIdx.x;
    int lt = blockIdx.x, bh = blockIdx.y;
    int b = bh >> 3, h = bh & 7;

    const float* vb = g_v + (size_t)bh * (512 * 32);

    // logits = (qk + rel) * scale   (16 rows x 512, fully coalesced reads)
    size_t base = ((size_t)(b * 512) + lt * 16) * 4096 + (size_t)h * 512;
    #pragma unroll
    for (int j = 0; j < 8; j++) {
        int idx = tid + j * 256;                 // [0, 2048)
        int row = idx >> 7, col4 = idx & 127;
        size_t g = base + (size_t)row * 4096 + col4 * 4;
        float4 a = *(const float4*)&g_qk[g];
        float4 c = *(const float4*)&g_rel[g];
        float4 o;
        o.x = (a.x + c.x) * SCALE_; o.y = (a.y + c.y) * SCALE_;
        o.z = (a.z + c.z) * SCALE_; o.w = (a.w + c.w) * SCALE_;
        *(float4*)&lg[row * AT_LG + col4 * 4] = o;
    }
    __syncthreads();

    // softmax: warp w handles rows 2w, 2w+1
    {
        int lane = tid & 31, w = tid >> 5;
        #pragma unroll
        for (int rr = 0; rr < 2; rr++) {
            float* row = &lg[(w * 2 + rr) * AT_LG];
            float vals[16];
            float mx = -1e30f;
            #pragma unroll
            for (int j = 0; j < 16; j++) { vals[j] = row[lane + 32 * j]; mx = fmaxf(mx, vals[j]); }
            #pragma unroll
            for (int o = 16; o > 0; o >>= 1) mx = fmaxf(mx, __shfl_xor_sync(0xffffffff, mx, o));
            float sum = 0.f;
            #pragma unroll
            for (int j = 0; j < 16; j++) {
                float e = __expf(vals[j] - mx);
                row[lane + 32 * j] = e;
                sum += e;
            }
            #pragma unroll
            for (int o = 16; o > 0; o >>= 1) sum += __shfl_xor_sync(0xffffffff, sum, o);
            if (lane == 0) inv_s[w * 2 + rr] = 1.f / sum;
        }
    }
    __syncthreads();

    // PV over 4 chunks of 128 m; thread = (l = tid>>4, d-pair dp = tid&15)
    int l = tid >> 4, dp = tid & 15;
    ull acc = 0ull;
    for (int mc = 0; mc < 4; mc++) {
        #pragma unroll
        for (int i = 0; i < 4; i++) {
            int idx = tid + i * 256;
            int r = idx >> 3, c4 = idx & 7;
            *(float4*)&vs[r * 36 + c4 * 4] =
                *(const float4*)&vb[(size_t)(mc * 128 + r) * 32 + c4 * 4];
        }
        __syncthreads();
        const float* lrow = &lg[l * AT_LG + mc * 128];
        #pragma unroll 8
        for (int m4 = 0; m4 < 32; m4++) {
            float4 p4 = *(const float4*)&lrow[m4 * 4];
            float pv[4] = {p4.x, p4.y, p4.z, p4.w};
            #pragma unroll
            for (int s = 0; s < 4; s++) {
                ull vv = *(const ull*)&vs[(m4 * 4 + s) * 36 + dp * 2];
                ffma2(acc, pack2(pv[s], pv[s]), vv);
            }
        }
        __syncthreads();
    }
    float o0, o1;
    unpack2(acc, o0, o1);
    float inv = inv_s[l];
    float2 o = make_float2(o0 * inv, o1 * inv);
    *(float2*)&g_att[((size_t)(b * 512) + lt * 16 + l) * 256 + h * 32 + dp * 2] = o;
}

// ===========================================================================
extern "C" void kernel_launch(void* const* d_in, const int* in_sizes, int n_in,
                              void* d_out, int out_size)
{
    const float* x      = (const float*)d_in[0];
    const float* rp     = (const float*)d_in[1];
    const float* w_qkv  = (const float*)d_in[2];
    const float* w_rel  = (const float*)d_in[3];
    const float* b_rel  = (const float*)d_in[4];
    const float* ln_g   = (const float*)d_in[5];
    const float* ln_b   = (const float*)d_in[6];
    const float* w_proj = (const float*)d_in[7];
    const float* b_proj = (const float*)d_in[8];
    float* out = (float*)d_out;

    static bool s_init = false;
    static cudaStream_t s_sB;
    static cudaEvent_t s_evF, s_evJ;
    if (!s_init) {
        cudaStreamCreateWithFlags(&s_sB, cudaStreamNonBlocking);
        cudaEventCreateWithFlags(&s_evF, cudaEventDisableTiming);
        cudaEventCreateWithFlags(&s_evJ, cudaEventDisableTiming);
        cudaFuncSetAttribute(attn2_kernel, cudaFuncAttributeMaxDynamicSharedMemorySize,
                             ATTN2_SMEM_FLOATS * (int)sizeof(float));
        s_init = true;
    }

    // fork: side stream runs qkv-gemm + qk while main stream runs relcompute
    cudaEventRecord(s_evF, 0);
    cudaStreamWaitEvent(s_sB, s_evF, 0);

    gemm_kernel<<<dim3(16, 24), 128, 0, s_sB>>>(x, w_qkv, nullptr, nullptr, 0);
    qk_kernel<<<dim3(16, 16, 2), 256, 0, s_sB>>>();

    rel_kernel<<<2048, 256>>>(rp, w_rel, b_rel, ln_g, ln_b);   // main stream

    // join
    cudaEventRecord(s_evJ, s_sB);
    cudaStreamWaitEvent(0, s_evJ, 0);

    attn2_kernel<<<dim3(32, 16), 256, ATTN2_SMEM_FLOATS * (int)sizeof(float)>>>();
    gemm_kernel<<<dim3(16, 8), 128>>>(nullptr, w_proj, b_proj, out, 1);
}